// round 4
// baseline (speedup 1.0000x reference)
#include <cuda_runtime.h>
#include <math.h>

#define NN  10000
#define NE  160000
#define TT  12
#define FIN 32
#define HH  64

typedef unsigned long long ull;

// ---------- packed f32x2 helpers ----------
__device__ __forceinline__ ull ffma2(ull a, ull b, ull c){
    ull d; asm("fma.rn.f32x2 %0, %1, %2, %3;" : "=l"(d) : "l"(a), "l"(b), "l"(c)); return d;
}
__device__ __forceinline__ ull pack2(float lo, float hi){
    ull r; asm("mov.b64 %0, {%1, %2};" : "=l"(r) : "f"(lo), "f"(hi)); return r;
}
__device__ __forceinline__ void unpack2(ull v, float& lo, float& hi){
    asm("mov.b64 {%0, %1}, %2;" : "=f"(lo), "=f"(hi) : "l"(v));
}

// ---------- scratch (device globals; no allocation allowed) ----------
__device__ int   g_is64;
__device__ int   g_cnt[NN];
__device__ int   g_off[NN];
__device__ int   g_cur[NN];
__device__ int   g_src[NE];
__device__ float g_dis[NN];
__device__ float g_aggx[NN * TT * FIN];   // aggregated input   (N,T,32)
__device__ float g_h0  [NN * TT * HH];    // gcn0 out           (N,T,64)
__device__ float g_agg1[NN * TT * HH];    // aggregated h0
__device__ float g_h1  [NN * TT * HH];    // gcn1 out = lstm0 in
__device__ float g_hs0 [NN * TT * HH];    // lstm0 out seq
__device__ float g_states[4][NN * HH];    // h0,c0,h1,c1

// ---------- edge dtype detection ----------
__global__ void k_detect(const int* __restrict__ w){
    int any = 0;
    #pragma unroll
    for (int i = 1; i < 129; i += 2) any |= w[i];
    g_is64 = (any == 0) ? 1 : 0;
}

__global__ void k_init(){
    int i = blockIdx.x * blockDim.x + threadIdx.x;
    if (i < NN) g_cnt[i] = 0;
}

__global__ void k_count(const void* __restrict__ ei){
    int e = blockIdx.x * blockDim.x + threadIdx.x;
    if (e >= NE) return;
    int c = g_is64 ? (int)((const long long*)ei)[NE + e]
                   : ((const int*)ei)[NE + e];
    atomicAdd(&g_cnt[c], 1);
}

// exclusive scan over counts; dis = rsqrt(deg+1 selfloop); cur = 0
__global__ void k_scan(){
    __shared__ int sh[1024];
    __shared__ int carry;
    int t = threadIdx.x;
    if (t == 0) carry = 0;
    __syncthreads();
    for (int base = 0; base < NN; base += 1024){
        int i = base + t;
        int v = (i < NN) ? g_cnt[i] : 0;
        sh[t] = v;
        __syncthreads();
        for (int d = 1; d < 1024; d <<= 1){
            int add = (t >= d) ? sh[t - d] : 0;
            __syncthreads();
            sh[t] += add;
            __syncthreads();
        }
        if (i < NN){
            g_off[i] = carry + sh[t] - v;
            g_cur[i] = 0;
            g_dis[i] = rsqrtf((float)(v + 1));
        }
        __syncthreads();
        if (t == 0) carry += sh[1023];
        __syncthreads();
    }
}

__global__ void k_fill(const void* __restrict__ ei){
    int e = blockIdx.x * blockDim.x + threadIdx.x;
    if (e >= NE) return;
    int r, c;
    if (g_is64){
        r = (int)((const long long*)ei)[e];
        c = (int)((const long long*)ei)[NE + e];
    } else {
        r = ((const int*)ei)[e];
        c = ((const int*)ei)[NE + e];
    }
    int p = atomicAdd(&g_cur[c], 1);
    g_src[g_off[c] + p] = r;
}

// ---------- aggregate raw input x (T,N,32) -> (N,T,32) ----------
__global__ void k_agg_x(const float* __restrict__ x){
    int c   = blockIdx.x;
    int off = g_off[c], len = g_cnt[c];
    float dc = g_dis[c];
    int t = threadIdx.x;                        // 128 thr, 384 positions
    int p0 = t, p1 = t + 128, p2 = t + 256;
    int b0 = (p0 >> 5) * (NN * FIN) + (p0 & 31);
    int b1 = (p1 >> 5) * (NN * FIN) + (p1 & 31);
    int b2 = (p2 >> 5) * (NN * FIN) + (p2 & 31);
    int cb = c * FIN;
    float a0 = dc * x[b0 + cb];
    float a1 = dc * x[b1 + cb];
    float a2 = dc * x[b2 + cb];
    for (int e = 0; e < len; ++e){
        int r = g_src[off + e];
        float dr = g_dis[r];
        int rb = r * FIN;
        a0 += dr * x[b0 + rb];
        a1 += dr * x[b1 + rb];
        a2 += dr * x[b2 + rb];
    }
    g_aggx[c * 384 + p0] = dc * a0;
    g_aggx[c * 384 + p1] = dc * a1;
    g_aggx[c * 384 + p2] = dc * a2;
}

// ---------- aggregate h0 (N,T,64) -> (N,T,64) ----------
__global__ void k_agg_h(){
    int c   = blockIdx.x;
    int off = g_off[c], len = g_cnt[c];
    float dc = g_dis[c];
    int t = threadIdx.x;                        // 256 thr, 768 positions
    int cb = c * 768;
    float a0 = dc * g_h0[cb + t];
    float a1 = dc * g_h0[cb + t + 256];
    float a2 = dc * g_h0[cb + t + 512];
    for (int e = 0; e < len; ++e){
        int r = g_src[off + e];
        float dr = g_dis[r];
        int rb = r * 768;
        a0 += dr * g_h0[rb + t];
        a1 += dr * g_h0[rb + t + 256];
        a2 += dr * g_h0[rb + t + 512];
    }
    g_agg1[cb + t]       = dc * a0;
    g_agg1[cb + t + 256] = dc * a1;
    g_agg1[cb + t + 512] = dc * a2;
}

// ---------- GCN GEMM: out = relu(A(M,K) @ W(K,64) + b); 96-row tiles ----------
template<int K>
__global__ __launch_bounds__(256)
void k_gcn_gemm(const float* __restrict__ W, const float* __restrict__ bvec){
    __shared__ __align__(16) float A_s[K * 98];     // pitch 98: 392B = 49*8, 8B-aligned
    __shared__ float W_s[K * 64];
    const float* __restrict__ A   = (K == FIN) ? g_aggx : g_agg1;
    float*       __restrict__ out = (K == FIN) ? g_h0  : g_h1;
    const int M = NN * TT;
    int t  = threadIdx.x;
    int nb = blockIdx.x * 96;

    for (int idx = t; idx < K * 64; idx += 256) W_s[idx] = W[idx];
    constexpr int KSH = (K == 32) ? 5 : 6;
    for (int idx = t; idx < 96 * K; idx += 256){
        int n = idx >> KSH, k = idx & (K - 1);
        A_s[k * 98 + n] = A[(nb + n) * K + k];      // exact tiling: nb+n < M
    }
    __syncthreads();

    int jj = t & 31, pg = t >> 5;                   // 8 warps x 12 rows (6 pairs)
    ull acc[6][2];
    #pragma unroll
    for (int p = 0; p < 6; ++p){ acc[p][0] = 0ull; acc[p][1] = 0ull; }

    #pragma unroll 8
    for (int k = 0; k < K; ++k){
        float w0 = W_s[k * 64 + jj], w1 = W_s[k * 64 + jj + 32];
        ull W0 = pack2(w0, w0), W1 = pack2(w1, w1);
        const float* Ar = &A_s[k * 98 + pg * 12];
        #pragma unroll
        for (int p = 0; p < 6; ++p){
            ull a = *(const ull*)(Ar + 2 * p);
            acc[p][0] = ffma2(a, W0, acc[p][0]);
            acc[p][1] = ffma2(a, W1, acc[p][1]);
        }
    }
    float b0 = bvec[jj], b1 = bvec[jj + 32];
    #pragma unroll
    for (int p = 0; p < 6; ++p){
        float v0l, v0h, v1l, v1h;
        unpack2(acc[p][0], v0l, v0h);
        unpack2(acc[p][1], v1l, v1h);
        int row = nb + pg * 12 + 2 * p;
        out[row * 64 + jj]            = fmaxf(v0l + b0, 0.f);
        out[row * 64 + jj + 32]       = fmaxf(v1l + b1, 0.f);
        out[(row + 1) * 64 + jj]      = fmaxf(v0h + b0, 0.f);
        out[(row + 1) * 64 + jj + 32] = fmaxf(v1h + b1, 0.f);
    }
}

__global__ void k_zero_states(){
    int i = blockIdx.x * blockDim.x + threadIdx.x;
    if (i < 4 * NN * HH) ((float*)g_states)[i] = 0.f;
}

// ---------- fused LSTM step: 64 nodes x 32 cols(jhalf) x 4 gates per block ----------
__global__ __launch_bounds__(256)
void k_lstm_step(int tstep, int layer,
                 const float* __restrict__ wih, const float* __restrict__ whh,
                 const float* __restrict__ bih, const float* __restrict__ bhh){
    __shared__ __align__(16) float A_s[128 * 66];   // [k][node]; 66*4=264B=33*8 aligned
    __shared__ float W_s[128 * 17];                 // 128 gate-rows x 16 k; pitch 17
    __shared__ float b_s[128];

    const float* __restrict__ xseq = layer ? g_hs0 : g_h1;
    float* __restrict__ hstate = g_states[2 * layer];
    float* __restrict__ cstate = g_states[2 * layer + 1];

    int t     = threadIdx.x;
    int tile  = blockIdx.x >> 1;
    int jhalf = blockIdx.x & 1;
    int nb    = tile * 64;

    for (int idx = t; idx < 64 * 128; idx += 256){
        int n = idx >> 7, k = idx & 127;
        int node = nb + n;
        float v = 0.f;
        if (node < NN)
            v = (k < 64) ? xseq[(node * TT + tstep) * 64 + k]
                         : hstate[node * 64 + (k - 64)];
        A_s[k * 66 + n] = v;
    }
    if (t < 128){
        int g = t >> 5, jr = t & 31;
        int gr = g * 64 + jhalf * 32 + jr;
        b_s[t] = bih[gr] + bhh[gr];
    }

    const int jj = t & 31;
    const int wg = t >> 5;                          // 8 groups x 8 nodes (4 pairs)
    ull acc[4][4];
    #pragma unroll
    for (int p = 0; p < 4; ++p)
        #pragma unroll
        for (int g = 0; g < 4; ++g) acc[p][g] = 0ull;

    for (int kc = 0; kc < 8; ++kc){
        __syncthreads();                            // covers A_s/b_s (kc=0) + W_s reuse
        int kglob = kc * 16;
        const float* __restrict__ Wsrc = (kglob < 64) ? wih : whh;
        int kbase = kglob & 63;
        for (int idx = t; idx < 128 * 16; idx += 256){
            int r = idx >> 4, kk = idx & 15;
            int g = r >> 5, jr = r & 31;
            W_s[r * 17 + kk] = Wsrc[(g * 64 + jhalf * 32 + jr) * 64 + kbase + kk];
        }
        __syncthreads();
        #pragma unroll 4
        for (int kk = 0; kk < 16; ++kk){
            const float* Ar = A_s + (kglob + kk) * 66 + wg * 8;
            ull a0 = *(const ull*)(Ar);
            ull a1 = *(const ull*)(Ar + 2);
            ull a2 = *(const ull*)(Ar + 4);
            ull a3 = *(const ull*)(Ar + 6);
            #pragma unroll
            for (int g = 0; g < 4; ++g){
                float w = W_s[(g * 32 + jj) * 17 + kk];
                ull W2 = pack2(w, w);
                acc[0][g] = ffma2(a0, W2, acc[0][g]);
                acc[1][g] = ffma2(a1, W2, acc[1][g]);
                acc[2][g] = ffma2(a2, W2, acc[2][g]);
                acc[3][g] = ffma2(a3, W2, acc[3][g]);
            }
        }
    }

    int col = jhalf * 32 + jj;
    float bi = b_s[jj], bf = b_s[32 + jj], bg = b_s[64 + jj], bo = b_s[96 + jj];
    #pragma unroll
    for (int p = 0; p < 4; ++p){
        float gl[4], gh[4];
        #pragma unroll
        for (int g = 0; g < 4; ++g) unpack2(acc[p][g], gl[g], gh[g]);
        #pragma unroll
        for (int half = 0; half < 2; ++half){
            int node = nb + wg * 8 + 2 * p + half;
            if (node >= NN) continue;
            float iv = (half ? gh[0] : gl[0]) + bi;
            float fv = (half ? gh[1] : gl[1]) + bf;
            float gv = (half ? gh[2] : gl[2]) + bg;
            float ov = (half ? gh[3] : gl[3]) + bo;
            float cold = cstate[node * 64 + col];
            float ig = 1.f / (1.f + __expf(-iv));
            float fg = 1.f / (1.f + __expf(-fv));
            float og = 1.f / (1.f + __expf(-ov));
            float cg = tanhf(gv);
            float cn = fg * cold + ig * cg;
            float hn = og * tanhf(cn);
            cstate[node * 64 + col] = cn;
            hstate[node * 64 + col] = hn;
            if (layer == 0)
                g_hs0[(node * TT + tstep) * 64 + col] = hn;
        }
    }
}

// ---------- final FC: out = h_last @ fc_w^T + fc_b ----------
__global__ void k_fc(const float* __restrict__ fw, const float* __restrict__ fb,
                     float* __restrict__ out){
    __shared__ float wsh[16 * 64];                  // [k][o]
    int t = threadIdx.x;
    for (int idx = t; idx < 1024; idx += 256){
        int k = idx >> 4, o = idx & 15;
        wsh[idx] = fw[o * 64 + k];
    }
    __syncthreads();
    int n = blockIdx.x * 16 + (t >> 4);
    int o = t & 15;
    if (n >= NN) return;
    const float* h = g_states[2];                   // layer-1 h after last step
    float acc = fb[o];
    #pragma unroll
    for (int k = 0; k < 64; ++k) acc += h[n * 64 + k] * wsh[k * 16 + o];
    out[n * 16 + o] = acc;
}

// ---------- launch ----------
extern "C" void kernel_launch(void* const* d_in, const int* in_sizes, int n_in,
                              void* d_out, int out_size){
    const float* x    = (const float*)d_in[0];
    const void*  ei   =               d_in[1];
    const float* gw0  = (const float*)d_in[2];
    const float* gb0  = (const float*)d_in[3];
    const float* gw1  = (const float*)d_in[4];
    const float* gb1  = (const float*)d_in[5];
    const float* wih0 = (const float*)d_in[6];
    const float* whh0 = (const float*)d_in[7];
    const float* bih0 = (const float*)d_in[8];
    const float* bhh0 = (const float*)d_in[9];
    const float* wih1 = (const float*)d_in[10];
    const float* whh1 = (const float*)d_in[11];
    const float* bih1 = (const float*)d_in[12];
    const float* bhh1 = (const float*)d_in[13];
    const float* fcw  = (const float*)d_in[14];
    const float* fcb  = (const float*)d_in[15];
    float* out = (float*)d_out;

    // CSR build
    k_init  <<<40, 256>>>();
    k_detect<<<1, 1>>>((const int*)ei);
    k_count <<<(NE + 255) / 256, 256>>>(ei);
    k_scan  <<<1, 1024>>>();
    k_fill  <<<(NE + 255) / 256, 256>>>(ei);

    // GCN layer 0: aggregate x (F=32), then GEMM+bias+relu
    k_agg_x<<<NN, 128>>>(x);
    k_gcn_gemm<32><<<1250, 256>>>(gw0, gb0);
    // GCN layer 1
    k_agg_h<<<NN, 256>>>();
    k_gcn_gemm<64><<<1250, 256>>>(gw1, gb1);

    // LSTM x2 (157 node-tiles x 2 col-halves = 314 blocks/step)
    k_zero_states<<<(4 * NN * HH + 255) / 256, 256>>>();
    for (int t = 0; t < TT; ++t)
        k_lstm_step<<<314, 256>>>(t, 0, wih0, whh0, bih0, bhh0);
    for (int t = 0; t < TT; ++t)
        k_lstm_step<<<314, 256>>>(t, 1, wih1, whh1, bih1, bhh1);

    // FC on last hidden state
    k_fc<<<(NN + 15) / 16, 256>>>(fcw, fcb, out);
}

// round 5
// speedup vs baseline: 1.1604x; 1.1604x over previous
#include <cuda_runtime.h>
#include <math.h>

#define NN  10000
#define NE  160000
#define TT  12
#define FIN 32
#define HH  64

typedef unsigned long long ull;

__device__ __forceinline__ ull ffma2(ull a, ull b, ull c){
    ull d; asm("fma.rn.f32x2 %0, %1, %2, %3;" : "=l"(d) : "l"(a), "l"(b), "l"(c)); return d;
}
__device__ __forceinline__ ull pack2(float lo, float hi){
    ull r; asm("mov.b64 %0, {%1, %2};" : "=l"(r) : "f"(lo), "f"(hi)); return r;
}
__device__ __forceinline__ void unpack2(ull v, float& lo, float& hi){
    asm("mov.b64 {%0, %1}, %2;" : "=f"(lo), "=f"(hi) : "l"(v));
}
__device__ __forceinline__ float fsig(float x){
    return __fdividef(1.f, 1.f + __expf(-x));
}
__device__ __forceinline__ float ftanh(float x){
    return 1.f - __fdividef(2.f, 1.f + __expf(2.f * x));
}

__device__ int   g_is64;
__device__ int   g_cnt[NN];
__device__ int   g_off[NN];
__device__ int   g_cur[NN];
__device__ int   g_src[NE];
__device__ float g_dis[NN];
__device__ float g_aggx[NN * TT * FIN];
__device__ float g_h0  [NN * TT * HH];
__device__ float g_agg1[NN * TT * HH];
__device__ float g_h1  [NN * TT * HH];
__device__ float g_hs0 [NN * TT * HH];
__device__ float g_pre [NN * TT * 256];
__device__ float g_states[4][NN * HH];

__global__ void k_detect(const int* __restrict__ w){
    int any = 0;
    #pragma unroll
    for (int i = 1; i < 129; i += 2) any |= w[i];
    g_is64 = (any == 0) ? 1 : 0;
}

__global__ void k_init(){
    int i = blockIdx.x * blockDim.x + threadIdx.x;
    if (i < NN) g_cnt[i] = 0;
}

__global__ void k_count(const void* __restrict__ ei){
    int e = blockIdx.x * blockDim.x + threadIdx.x;
    if (e >= NE) return;
    int c = g_is64 ? (int)((const long long*)ei)[NE + e]
                   : ((const int*)ei)[NE + e];
    atomicAdd(&g_cnt[c], 1);
}

__global__ void k_scan(){
    const int PER = 10;
    int t = threadIdx.x;
    int lane = t & 31, w = t >> 5;
    int base = t * PER;
    int v[PER];
    int s = 0;
    #pragma unroll
    for (int i = 0; i < PER; ++i){
        int idx = base + i;
        v[i] = (idx < NN) ? g_cnt[idx] : 0;
        s += v[i];
    }
    int incl = s;
    #pragma unroll
    for (int d = 1; d < 32; d <<= 1){
        int o = __shfl_up_sync(0xffffffffu, incl, d);
        if (lane >= d) incl += o;
    }
    __shared__ int wsum[32];
    if (lane == 31) wsum[w] = incl;
    __syncthreads();
    if (w == 0){
        int x = wsum[lane];
        int i2 = x;
        #pragma unroll
        for (int d = 1; d < 32; d <<= 1){
            int o = __shfl_up_sync(0xffffffffu, i2, d);
            if (lane >= d) i2 += o;
        }
        wsum[lane] = i2 - x;
    }
    __syncthreads();
    int run = wsum[w] + incl - s;
    #pragma unroll
    for (int i = 0; i < PER; ++i){
        int idx = base + i;
        if (idx < NN){
            g_off[idx] = run;
            g_cur[idx] = 0;
            g_dis[idx] = rsqrtf((float)(v[i] + 1));
            run += v[i];
        }
    }
}

__global__ void k_fill(const void* __restrict__ ei){
    int e = blockIdx.x * blockDim.x + threadIdx.x;
    if (e >= NE) return;
    int r, c;
    if (g_is64){
        r = (int)((const long long*)ei)[e];
        c = (int)((const long long*)ei)[NE + e];
    } else {
        r = ((const int*)ei)[e];
        c = ((const int*)ei)[NE + e];
    }
    int p = atomicAdd(&g_cur[c], 1);
    g_src[g_off[c] + p] = r;
}

__global__ void k_agg_x(const float* __restrict__ x){
    int c   = blockIdx.x;
    int off = g_off[c], len = g_cnt[c];
    float dc = g_dis[c];
    int t = threadIdx.x;
    int p0 = t, p1 = t + 128, p2 = t + 256;
    int b0 = (p0 >> 5) * (NN * FIN) + (p0 & 31);
    int b1 = (p1 >> 5) * (NN * FIN) + (p1 & 31);
    int b2 = (p2 >> 5) * (NN * FIN) + (p2 & 31);
    int cb = c * FIN;
    float a0 = dc * x[b0 + cb];
    float a1 = dc * x[b1 + cb];
    float a2 = dc * x[b2 + cb];
    for (int e = 0; e < len; ++e){
        int r = g_src[off + e];
        float dr = g_dis[r];
        int rb = r * FIN;
        a0 += dr * x[b0 + rb];
        a1 += dr * x[b1 + rb];
        a2 += dr * x[b2 + rb];
    }
    g_aggx[c * 384 + p0] = dc * a0;
    g_aggx[c * 384 + p1] = dc * a1;
    g_aggx[c * 384 + p2] = dc * a2;
}

__global__ void k_agg_h(){
    int c   = blockIdx.x;
    int off = g_off[c], len = g_cnt[c];
    float dc = g_dis[c];
    int t = threadIdx.x;
    int cb = c * 768;
    float a0 = dc * g_h0[cb + t];
    float a1 = dc * g_h0[cb + t + 256];
    float a2 = dc * g_h0[cb + t + 512];
    for (int e = 0; e < len; ++e){
        int r = g_src[off + e];
        float dr = g_dis[r];
        int rb = r * 768;
        a0 += dr * g_h0[rb + t];
        a1 += dr * g_h0[rb + t + 256];
        a2 += dr * g_h0[rb + t + 512];
    }
    g_agg1[cb + t]       = dc * a0;
    g_agg1[cb + t + 256] = dc * a1;
    g_agg1[cb + t + 512] = dc * a2;
}

template<int K>
__global__ __launch_bounds__(256)
void k_gcn_gemm(const float* __restrict__ W, const float* __restrict__ bvec){
    __shared__ __align__(16) float A_s[K * 98];
    __shared__ float W_s[K * 64];
    const float* __restrict__ A   = (K == FIN) ? g_aggx : g_agg1;
    float*       __restrict__ out = (K == FIN) ? g_h0  : g_h1;
    int t  = threadIdx.x;
    int nb = blockIdx.x * 96;

    for (int idx = t; idx < K * 64; idx += 256) W_s[idx] = W[idx];
    constexpr int KSH = (K == 32) ? 5 : 6;
    for (int idx = t; idx < 96 * K; idx += 256){
        int n = idx >> KSH, k = idx & (K - 1);
        A_s[k * 98 + n] = A[(nb + n) * K + k];
    }
    __syncthreads();

    int jj = t & 31, pg = t >> 5;
    ull acc[6][2];
    #pragma unroll
    for (int p = 0; p < 6; ++p){ acc[p][0] = 0ull; acc[p][1] = 0ull; }

    #pragma unroll 8
    for (int k = 0; k < K; ++k){
        float w0 = W_s[k * 64 + jj], w1 = W_s[k * 64 + jj + 32];
        ull W0 = pack2(w0, w0), W1 = pack2(w1, w1);
        const float* Ar = &A_s[k * 98 + pg * 12];
        #pragma unroll
        for (int p = 0; p < 6; ++p){
            ull a = *(const ull*)(Ar + 2 * p);
            acc[p][0] = ffma2(a, W0, acc[p][0]);
            acc[p][1] = ffma2(a, W1, acc[p][1]);
        }
    }
    float b0 = bvec[jj], b1 = bvec[jj + 32];
    #pragma unroll
    for (int p = 0; p < 6; ++p){
        float v0l, v0h, v1l, v1h;
        unpack2(acc[p][0], v0l, v0h);
        unpack2(acc[p][1], v1l, v1h);
        int row = nb + pg * 12 + 2 * p;
        out[row * 64 + jj]            = fmaxf(v0l + b0, 0.f);
        out[row * 64 + jj + 32]       = fmaxf(v1l + b1, 0.f);
        out[(row + 1) * 64 + jj]      = fmaxf(v0h + b0, 0.f);
        out[(row + 1) * 64 + jj + 32] = fmaxf(v1h + b1, 0.f);
    }
}

// xseq_sel: 0 -> g_h1, 1 -> g_hs0
__global__ __launch_bounds__(256)
void k_xproj(int xseq_sel, const float* __restrict__ wih,
             const float* __restrict__ bih, const float* __restrict__ bhh){
    __shared__ __align__(16) float A_s[64 * 98];
    __shared__ float W_s[64 * 65];
    __shared__ float b_s[64];
    const float* __restrict__ xseq = xseq_sel ? g_hs0 : g_h1;
    int t  = threadIdx.x;
    int nb = blockIdx.x * 96;
    int cb = blockIdx.y * 64;

    for (int idx = t; idx < 64 * 64; idx += 256){
        int k = idx & 63, j = idx >> 6;
        W_s[k * 65 + j] = wih[(cb + j) * 64 + k];
    }
    if (t < 64) b_s[t] = bih[cb + t] + bhh[cb + t];
    for (int idx = t; idx < 96 * 64; idx += 256){
        int n = idx >> 6, k = idx & 63;
        A_s[k * 98 + n] = xseq[(nb + n) * 64 + k];
    }
    __syncthreads();

    int jj = t & 31, pg = t >> 5;
    ull acc[6][2];
    #pragma unroll
    for (int p = 0; p < 6; ++p){ acc[p][0] = 0ull; acc[p][1] = 0ull; }

    #pragma unroll 8
    for (int k = 0; k < 64; ++k){
        float w0 = W_s[k * 65 + jj], w1 = W_s[k * 65 + jj + 32];
        ull W0 = pack2(w0, w0), W1 = pack2(w1, w1);
        const float* Ar = &A_s[k * 98 + pg * 12];
        #pragma unroll
        for (int p = 0; p < 6; ++p){
            ull a = *(const ull*)(Ar + 2 * p);
            acc[p][0] = ffma2(a, W0, acc[p][0]);
            acc[p][1] = ffma2(a, W1, acc[p][1]);
        }
    }
    float b0 = b_s[jj], b1 = b_s[jj + 32];
    #pragma unroll
    for (int p = 0; p < 6; ++p){
        float v0l, v0h, v1l, v1h;
        unpack2(acc[p][0], v0l, v0h);
        unpack2(acc[p][1], v1l, v1h);
        int row = nb + pg * 12 + 2 * p;
        g_pre[row * 256 + cb + jj]            = v0l + b0;
        g_pre[row * 256 + cb + jj + 32]       = v1l + b1;
        g_pre[(row + 1) * 256 + cb + jj]      = v0h + b0;
        g_pre[(row + 1) * 256 + cb + jj + 32] = v1h + b1;
    }
}

__global__ void k_zero_states(){
    int i = blockIdx.x * blockDim.x + threadIdx.x;
    if (i < 4 * NN * HH) ((float*)g_states)[i] = 0.f;
}

__global__ __launch_bounds__(256)
void k_lstm_step(int tstep, int layer, const float* __restrict__ whh){
    __shared__ __align__(16) float A_s[64 * 66];
    __shared__ float W_s[128 * 17];

    float* __restrict__ hstate = g_states[2 * layer];
    float* __restrict__ cstate = g_states[2 * layer + 1];

    int t     = threadIdx.x;
    int tile  = blockIdx.x >> 1;
    int jhalf = blockIdx.x & 1;
    int nb    = tile * 64;

    for (int idx = t; idx < 64 * 64; idx += 256){
        int n = idx >> 6, k = idx & 63;
        int node = nb + n;
        A_s[k * 66 + n] = (node < NN) ? hstate[node * 64 + k] : 0.f;
    }

    const int jj = t & 31;
    const int wg = t >> 5;
    ull acc[4][4];
    #pragma unroll
    for (int p = 0; p < 4; ++p)
        #pragma unroll
        for (int g = 0; g < 4; ++g) acc[p][g] = 0ull;

    for (int kc = 0; kc < 4; ++kc){
        __syncthreads();
        int kglob = kc * 16;
        for (int idx = t; idx < 128 * 16; idx += 256){
            int r = idx >> 4, kk = idx & 15;
            int g = r >> 5, jr = r & 31;
            W_s[r * 17 + kk] = whh[(g * 64 + jhalf * 32 + jr) * 64 + kglob + kk];
        }
        __syncthreads();
        #pragma unroll 4
        for (int kk = 0; kk < 16; ++kk){
            const float* Ar = A_s + (kglob + kk) * 66 + wg * 8;
            ull a0 = *(const ull*)(Ar);
            ull a1 = *(const ull*)(Ar + 2);
            ull a2 = *(const ull*)(Ar + 4);
            ull a3 = *(const ull*)(Ar + 6);
            #pragma unroll
            for (int g = 0; g < 4; ++g){
                float w = W_s[(g * 32 + jj) * 17 + kk];
                ull W2 = pack2(w, w);
                acc[0][g] = ffma2(a0, W2, acc[0][g]);
                acc[1][g] = ffma2(a1, W2, acc[1][g]);
                acc[2][g] = ffma2(a2, W2, acc[2][g]);
                acc[3][g] = ffma2(a3, W2, acc[3][g]);
            }
        }
    }

    int col = jhalf * 32 + jj;
    #pragma unroll
    for (int p = 0; p < 4; ++p){
        float gl[4], gh[4];
        #pragma unroll
        for (int g = 0; g < 4; ++g) unpack2(acc[p][g], gl[g], gh[g]);
        #pragma unroll
        for (int half = 0; half < 2; ++half){
            int node = nb + wg * 8 + 2 * p + half;
            if (node >= NN) continue;
            const float* pre = &g_pre[(node * TT + tstep) * 256 + col];
            float iv = (half ? gh[0] : gl[0]) + pre[0];
            float fv = (half ? gh[1] : gl[1]) + pre[64];
            float gv = (half ? gh[2] : gl[2]) + pre[128];
            float ov = (half ? gh[3] : gl[3]) + pre[192];
            float cold = cstate[node * 64 + col];
            float cn = fsig(fv) * cold + fsig(iv) * ftanh(gv);
            float hn = fsig(ov) * ftanh(cn);
            cstate[node * 64 + col] = cn;
            hstate[node * 64 + col] = hn;
            if (layer == 0)
                g_hs0[(node * TT + tstep) * 64 + col] = hn;
        }
    }
}

__global__ void k_fc(const float* __restrict__ fw, const float* __restrict__ fb,
                     float* __restrict__ out){
    __shared__ float wsh[16 * 64];
    int t = threadIdx.x;
    for (int idx = t; idx < 1024; idx += 256){
        int k = idx >> 4, o = idx & 15;
        wsh[idx] = fw[o * 64 + k];
    }
    __syncthreads();
    int n = blockIdx.x * 16 + (t >> 4);
    int o = t & 15;
    if (n >= NN) return;
    const float* h = g_states[2];
    float acc = fb[o];
    #pragma unroll
    for (int k = 0; k < 64; ++k) acc += h[n * 64 + k] * wsh[k * 16 + o];
    out[n * 16 + o] = acc;
}

extern "C" void kernel_launch(void* const* d_in, const int* in_sizes, int n_in,
                              void* d_out, int out_size){
    const float* x    = (const float*)d_in[0];
    const void*  ei   =               d_in[1];
    const float* gw0  = (const float*)d_in[2];
    const float* gb0  = (const float*)d_in[3];
    const float* gw1  = (const float*)d_in[4];
    const float* gb1  = (const float*)d_in[5];
    const float* wih0 = (const float*)d_in[6];
    const float* whh0 = (const float*)d_in[7];
    const float* bih0 = (const float*)d_in[8];
    const float* bhh0 = (const float*)d_in[9];
    const float* wih1 = (const float*)d_in[10];
    const float* whh1 = (const float*)d_in[11];
    const float* bih1 = (const float*)d_in[12];
    const float* bhh1 = (const float*)d_in[13];
    const float* fcw  = (const float*)d_in[14];
    const float* fcb  = (const float*)d_in[15];
    float* out = (float*)d_out;

    k_init  <<<40, 256>>>();
    k_detect<<<1, 1>>>((const int*)ei);
    k_count <<<(NE + 255) / 256, 256>>>(ei);
    k_scan  <<<1, 1024>>>();
    k_fill  <<<(NE + 255) / 256, 256>>>(ei);

    k_agg_x<<<NN, 128>>>(x);
    k_gcn_gemm<32><<<1250, 256>>>(gw0, gb0);
    k_agg_h<<<NN, 256>>>();
    k_gcn_gemm<64><<<1250, 256>>>(gw1, gb1);

    k_zero_states<<<(4 * NN * HH + 255) / 256, 256>>>();

    dim3 gx(1250, 4);
    k_xproj<<<gx, 256>>>(0, wih0, bih0, bhh0);
    for (int t = 0; t < TT; ++t)
        k_lstm_step<<<314, 256>>>(t, 0, whh0);

    k_xproj<<<gx, 256>>>(1, wih1, bih1, bhh1);
    for (int t = 0; t < TT; ++t)
        k_lstm_step<<<314, 256>>>(t, 1, whh1);

    k_fc<<<(NN + 15) / 16, 256>>>(fcw, fcb, out);
}

// round 6
// speedup vs baseline: 1.3390x; 1.1539x over previous
#include <cuda_runtime.h>
#include <math.h>

#define NN  10000
#define NE  160000
#define TT  12
#define FIN 32
#define HH  64

typedef unsigned long long ull;

__device__ __forceinline__ ull ffma2(ull a, ull b, ull c){
    ull d; asm("fma.rn.f32x2 %0, %1, %2, %3;" : "=l"(d) : "l"(a), "l"(b), "l"(c)); return d;
}
__device__ __forceinline__ ull pack2(float lo, float hi){
    ull r; asm("mov.b64 %0, {%1, %2};" : "=l"(r) : "f"(lo), "f"(hi)); return r;
}
__device__ __forceinline__ void unpack2(ull v, float& lo, float& hi){
    asm("mov.b64 {%0, %1}, %2;" : "=f"(lo), "=f"(hi) : "l"(v));
}
__device__ __forceinline__ float fsig(float x){
    return __fdividef(1.f, 1.f + __expf(-x));
}
__device__ __forceinline__ float ftanh(float x){
    return 1.f - __fdividef(2.f, 1.f + __expf(2.f * x));
}

__device__ int   g_is64;
__device__ int   g_cnt[NN];
__device__ int   g_off[NN];
__device__ int   g_cur[NN];
__device__ int   g_src[NE];
__device__ int   g_bsum[80];
__device__ int   g_bbase[80];
__device__ float g_dis[NN];
__device__ float g_aggx[NN * TT * FIN];
__device__ float g_h0  [NN * TT * HH];
__device__ float g_agg1[NN * TT * HH];
__device__ float g_h1  [NN * TT * HH];
__device__ float g_hs0 [NN * TT * HH];
__device__ float g_pre [NN * TT * 256];
__device__ float g_hlast[NN * HH];

// ---------- CSR build ----------
__global__ void k_init(const int* __restrict__ w){
    int i = blockIdx.x * blockDim.x + threadIdx.x;
    if (i < NN) g_cnt[i] = 0;
    if (blockIdx.x == 0 && threadIdx.x == 0){
        int any = 0;
        #pragma unroll
        for (int j = 1; j < 129; j += 2) any |= w[j];
        g_is64 = (any == 0) ? 1 : 0;
    }
}

__global__ void k_count(const void* __restrict__ ei){
    int e = blockIdx.x * blockDim.x + threadIdx.x;
    if (e >= NE) return;
    int c = g_is64 ? (int)((const long long*)ei)[NE + e]
                   : ((const int*)ei)[NE + e];
    atomicAdd(&g_cnt[c], 1);
}

__global__ void k_scan1(){
    int b = blockIdx.x, t = threadIdx.x;
    int i = b * 128 + t;
    int v = (i < NN) ? g_cnt[i] : 0;
    int lane = t & 31, w = t >> 5;
    int s = v;
    #pragma unroll
    for (int d = 16; d > 0; d >>= 1) s += __shfl_down_sync(0xffffffffu, s, d);
    __shared__ int ws[4];
    if (lane == 0) ws[w] = s;
    __syncthreads();
    if (t == 0) g_bsum[b] = ws[0] + ws[1] + ws[2] + ws[3];
}

__global__ void k_scan2(){
    int t = threadIdx.x;
    int v = (t < 79) ? g_bsum[t] : 0;
    int lane = t & 31, w = t >> 5;
    int incl = v;
    #pragma unroll
    for (int d = 1; d < 32; d <<= 1){
        int o = __shfl_up_sync(0xffffffffu, incl, d);
        if (lane >= d) incl += o;
    }
    __shared__ int ws[4];
    if (lane == 31) ws[w] = incl;
    __syncthreads();
    int base = 0;
    for (int i = 0; i < w; ++i) base += ws[i];
    if (t < 79) g_bbase[t] = base + incl - v;
}

__global__ void k_scan3(){
    int b = blockIdx.x, t = threadIdx.x;
    int i = b * 128 + t;
    int v = (i < NN) ? g_cnt[i] : 0;
    int lane = t & 31, w = t >> 5;
    int incl = v;
    #pragma unroll
    for (int d = 1; d < 32; d <<= 1){
        int o = __shfl_up_sync(0xffffffffu, incl, d);
        if (lane >= d) incl += o;
    }
    __shared__ int ws[4];
    if (lane == 31) ws[w] = incl;
    __syncthreads();
    int base = g_bbase[b];
    for (int k = 0; k < w; ++k) base += ws[k];
    if (i < NN){
        g_off[i] = base + incl - v;
        g_cur[i] = 0;
        g_dis[i] = rsqrtf((float)(v + 1));
    }
}

__global__ void k_fill(const void* __restrict__ ei){
    int e = blockIdx.x * blockDim.x + threadIdx.x;
    if (e >= NE) return;
    int r, c;
    if (g_is64){
        r = (int)((const long long*)ei)[e];
        c = (int)((const long long*)ei)[NE + e];
    } else {
        r = ((const int*)ei)[e];
        c = ((const int*)ei)[NE + e];
    }
    int p = atomicAdd(&g_cur[c], 1);
    g_src[g_off[c] + p] = r;
}

// ---------- aggregations ----------
__global__ void k_agg_x(const float* __restrict__ x){
    int c   = blockIdx.x;
    int off = g_off[c], len = g_cnt[c];
    float dc = g_dis[c];
    int t = threadIdx.x;
    int p0 = t, p1 = t + 128, p2 = t + 256;
    int b0 = (p0 >> 5) * (NN * FIN) + (p0 & 31);
    int b1 = (p1 >> 5) * (NN * FIN) + (p1 & 31);
    int b2 = (p2 >> 5) * (NN * FIN) + (p2 & 31);
    int cb = c * FIN;
    float a0 = dc * x[b0 + cb];
    float a1 = dc * x[b1 + cb];
    float a2 = dc * x[b2 + cb];
    for (int e = 0; e < len; ++e){
        int r = g_src[off + e];
        float dr = g_dis[r];
        int rb = r * FIN;
        a0 += dr * x[b0 + rb];
        a1 += dr * x[b1 + rb];
        a2 += dr * x[b2 + rb];
    }
    g_aggx[c * 384 + p0] = dc * a0;
    g_aggx[c * 384 + p1] = dc * a1;
    g_aggx[c * 384 + p2] = dc * a2;
}

__global__ void k_agg_h(){
    int c   = blockIdx.x;
    int off = g_off[c], len = g_cnt[c];
    float dc = g_dis[c];
    int t = threadIdx.x;
    int cb = c * 768;
    float a0 = dc * g_h0[cb + t];
    float a1 = dc * g_h0[cb + t + 256];
    float a2 = dc * g_h0[cb + t + 512];
    for (int e = 0; e < len; ++e){
        int r = g_src[off + e];
        float dr = g_dis[r];
        int rb = r * 768;
        a0 += dr * g_h0[rb + t];
        a1 += dr * g_h0[rb + t + 256];
        a2 += dr * g_h0[rb + t + 512];
    }
    g_agg1[cb + t]       = dc * a0;
    g_agg1[cb + t + 256] = dc * a1;
    g_agg1[cb + t + 512] = dc * a2;
}

// ---------- GCN GEMM ----------
template<int K>
__global__ __launch_bounds__(256)
void k_gcn_gemm(const float* __restrict__ W, const float* __restrict__ bvec){
    __shared__ __align__(16) float A_s[K * 98];
    __shared__ float W_s[K * 64];
    const float* __restrict__ A   = (K == FIN) ? g_aggx : g_agg1;
    float*       __restrict__ out = (K == FIN) ? g_h0  : g_h1;
    int t  = threadIdx.x;
    int nb = blockIdx.x * 96;

    for (int idx = t; idx < K * 64; idx += 256) W_s[idx] = W[idx];
    constexpr int KSH = (K == 32) ? 5 : 6;
    for (int idx = t; idx < 96 * K; idx += 256){
        int n = idx >> KSH, k = idx & (K - 1);
        A_s[k * 98 + n] = A[(nb + n) * K + k];
    }
    __syncthreads();

    int jj = t & 31, pg = t >> 5;
    ull acc[6][2];
    #pragma unroll
    for (int p = 0; p < 6; ++p){ acc[p][0] = 0ull; acc[p][1] = 0ull; }

    #pragma unroll 8
    for (int k = 0; k < K; ++k){
        float w0 = W_s[k * 64 + jj], w1 = W_s[k * 64 + jj + 32];
        ull W0 = pack2(w0, w0), W1 = pack2(w1, w1);
        const float* Ar = &A_s[k * 98 + pg * 12];
        #pragma unroll
        for (int p = 0; p < 6; ++p){
            ull a = *(const ull*)(Ar + 2 * p);
            acc[p][0] = ffma2(a, W0, acc[p][0]);
            acc[p][1] = ffma2(a, W1, acc[p][1]);
        }
    }
    float b0 = bvec[jj], b1 = bvec[jj + 32];
    #pragma unroll
    for (int p = 0; p < 6; ++p){
        float v0l, v0h, v1l, v1h;
        unpack2(acc[p][0], v0l, v0h);
        unpack2(acc[p][1], v1l, v1h);
        int row = nb + pg * 12 + 2 * p;
        out[row * 64 + jj]            = fmaxf(v0l + b0, 0.f);
        out[row * 64 + jj + 32]       = fmaxf(v1l + b1, 0.f);
        out[(row + 1) * 64 + jj]      = fmaxf(v0h + b0, 0.f);
        out[(row + 1) * 64 + jj + 32] = fmaxf(v1h + b1, 0.f);
    }
}

// ---------- hoisted input projection (xseq_sel: 0 -> g_h1, 1 -> g_hs0) ----------
__global__ __launch_bounds__(256)
void k_xproj(int xseq_sel, const float* __restrict__ wih,
             const float* __restrict__ bih, const float* __restrict__ bhh){
    __shared__ __align__(16) float A_s[64 * 98];
    __shared__ float W_s[64 * 65];
    __shared__ float b_s[64];
    const float* __restrict__ xseq = xseq_sel ? g_hs0 : g_h1;
    int t  = threadIdx.x;
    int nb = blockIdx.x * 96;
    int cb = blockIdx.y * 64;

    for (int idx = t; idx < 64 * 64; idx += 256){
        int k = idx & 63, j = idx >> 6;
        W_s[k * 65 + j] = wih[(cb + j) * 64 + k];
    }
    if (t < 64) b_s[t] = bih[cb + t] + bhh[cb + t];
    for (int idx = t; idx < 96 * 64; idx += 256){
        int n = idx >> 6, k = idx & 63;
        A_s[k * 98 + n] = xseq[(nb + n) * 64 + k];
    }
    __syncthreads();

    int jj = t & 31, pg = t >> 5;
    ull acc[6][2];
    #pragma unroll
    for (int p = 0; p < 6; ++p){ acc[p][0] = 0ull; acc[p][1] = 0ull; }

    #pragma unroll 8
    for (int k = 0; k < 64; ++k){
        float w0 = W_s[k * 65 + jj], w1 = W_s[k * 65 + jj + 32];
        ull W0 = pack2(w0, w0), W1 = pack2(w1, w1);
        const float* Ar = &A_s[k * 98 + pg * 12];
        #pragma unroll
        for (int p = 0; p < 6; ++p){
            ull a = *(const ull*)(Ar + 2 * p);
            acc[p][0] = ffma2(a, W0, acc[p][0]);
            acc[p][1] = ffma2(a, W1, acc[p][1]);
        }
    }
    float b0 = b_s[jj], b1 = b_s[jj + 32];
    #pragma unroll
    for (int p = 0; p < 6; ++p){
        float v0l, v0h, v1l, v1h;
        unpack2(acc[p][0], v0l, v0h);
        unpack2(acc[p][1], v1l, v1h);
        int row = nb + pg * 12 + 2 * p;
        g_pre[row * 256 + cb + jj]            = v0l + b0;
        g_pre[row * 256 + cb + jj + 32]       = v1l + b1;
        g_pre[(row + 1) * 256 + cb + jj]      = v0h + b0;
        g_pre[(row + 1) * 256 + cb + jj + 32] = v1h + b1;
    }
}

// ---------- persistent per-layer LSTM: 125 blocks x 80 nodes, 12 steps ----------
// smem: Whh (256x65), h (64x82), c (64x82) — all resident across steps.
#define LSTM_SMEM ((256 * 65 + 64 * 82 + 64 * 82) * 4)

__global__ __launch_bounds__(256, 1)
void k_lstm_layer(int layer, const float* __restrict__ whh){
    extern __shared__ float smem[];
    float* W_s = smem;                 // [c 0..255][kk 0..63], pitch 65
    float* h_s = smem + 256 * 65;      // [k 0..63][n 0..79], pitch 82
    float* c_s = h_s + 64 * 82;        // [hcol][n], pitch 82

    int t  = threadIdx.x;
    int jj = t & 31, wg = t >> 5;
    int nb = blockIdx.x * 80;

    for (int idx = t; idx < 256 * 64; idx += 256){
        int k = idx & 63, c = idx >> 6;
        W_s[c * 65 + k] = whh[idx];
    }
    for (int idx = t; idx < 64 * 82; idx += 256){
        h_s[idx] = 0.f;
        c_s[idx] = 0.f;
    }
    __syncthreads();

    for (int st = 0; st < TT; ++st){
        ull acc[8][5];
        #pragma unroll
        for (int g = 0; g < 8; ++g)
            #pragma unroll
            for (int p = 0; p < 5; ++p) acc[g][p] = 0ull;

        #pragma unroll 4
        for (int kk = 0; kk < 64; ++kk){
            const float* Ar = h_s + kk * 82 + wg * 10;
            ull a0 = *(const ull*)(Ar + 0);
            ull a1 = *(const ull*)(Ar + 2);
            ull a2 = *(const ull*)(Ar + 4);
            ull a3 = *(const ull*)(Ar + 6);
            ull a4 = *(const ull*)(Ar + 8);
            #pragma unroll
            for (int g = 0; g < 8; ++g){
                float w = W_s[(jj + 32 * g) * 65 + kk];
                ull W2 = pack2(w, w);
                acc[g][0] = ffma2(a0, W2, acc[g][0]);
                acc[g][1] = ffma2(a1, W2, acc[g][1]);
                acc[g][2] = ffma2(a2, W2, acc[g][2]);
                acc[g][3] = ffma2(a3, W2, acc[g][3]);
                acc[g][4] = ffma2(a4, W2, acc[g][4]);
            }
        }
        __syncthreads();                       // all reads of h_s done

        #pragma unroll
        for (int p = 0; p < 5; ++p){
            #pragma unroll
            for (int hs2 = 0; hs2 < 2; ++hs2){
                int hcol = jj + 32 * hs2;
                float i0, i1, f0, f1, g0, g1, o0, o1;
                unpack2(acc[0 + hs2][p], i0, i1);
                unpack2(acc[2 + hs2][p], f0, f1);
                unpack2(acc[4 + hs2][p], g0, g1);
                unpack2(acc[6 + hs2][p], o0, o1);
                #pragma unroll
                for (int half = 0; half < 2; ++half){
                    int nloc = wg * 10 + 2 * p + half;
                    int node = nb + nloc;
                    const float* pre = g_pre + (node * TT + st) * 256 + hcol;
                    float iv = (half ? i1 : i0) + pre[0];
                    float fv = (half ? f1 : f0) + pre[64];
                    float gv = (half ? g1 : g0) + pre[128];
                    float ov = (half ? o1 : o0) + pre[192];
                    float cold = c_s[hcol * 82 + nloc];
                    float cn = fsig(fv) * cold + fsig(iv) * ftanh(gv);
                    float hn = fsig(ov) * ftanh(cn);
                    c_s[hcol * 82 + nloc] = cn;
                    h_s[hcol * 82 + nloc] = hn;
                    if (layer == 0)
                        g_hs0[(node * TT + st) * 64 + hcol] = hn;
                    else if (st == TT - 1)
                        g_hlast[node * 64 + hcol] = hn;
                }
            }
        }
        __syncthreads();                       // h_s fully updated
    }
}

// ---------- final FC ----------
__global__ void k_fc(const float* __restrict__ fw, const float* __restrict__ fb,
                     float* __restrict__ out){
    __shared__ float wsh[16 * 64];
    int t = threadIdx.x;
    for (int idx = t; idx < 1024; idx += 256){
        int k = idx >> 4, o = idx & 15;
        wsh[idx] = fw[o * 64 + k];
    }
    __syncthreads();
    int n = blockIdx.x * 16 + (t >> 4);
    int o = t & 15;
    if (n >= NN) return;
    float acc = fb[o];
    #pragma unroll
    for (int k = 0; k < 64; ++k) acc += g_hlast[n * 64 + k] * wsh[k * 16 + o];
    out[n * 16 + o] = acc;
}

extern "C" void kernel_launch(void* const* d_in, const int* in_sizes, int n_in,
                              void* d_out, int out_size){
    const float* x    = (const float*)d_in[0];
    const void*  ei   =               d_in[1];
    const float* gw0  = (const float*)d_in[2];
    const float* gb0  = (const float*)d_in[3];
    const float* gw1  = (const float*)d_in[4];
    const float* gb1  = (const float*)d_in[5];
    const float* wih0 = (const float*)d_in[6];
    const float* whh0 = (const float*)d_in[7];
    const float* bih0 = (const float*)d_in[8];
    const float* bhh0 = (const float*)d_in[9];
    const float* wih1 = (const float*)d_in[10];
    const float* whh1 = (const float*)d_in[11];
    const float* bih1 = (const float*)d_in[12];
    const float* bhh1 = (const float*)d_in[13];
    const float* fcw  = (const float*)d_in[14];
    const float* fcb  = (const float*)d_in[15];
    float* out = (float*)d_out;

    cudaFuncSetAttribute(k_lstm_layer,
                         cudaFuncAttributeMaxDynamicSharedMemorySize, LSTM_SMEM);

    // CSR build (parallel 3-phase scan)
    k_init <<<40, 256>>>((const int*)ei);
    k_count<<<(NE + 255) / 256, 256>>>(ei);
    k_scan1<<<79, 128>>>();
    k_scan2<<<1, 128>>>();
    k_scan3<<<79, 128>>>();
    k_fill <<<(NE + 255) / 256, 256>>>(ei);

    // GCN
    k_agg_x<<<NN, 128>>>(x);
    k_gcn_gemm<32><<<1250, 256>>>(gw0, gb0);
    k_agg_h<<<NN, 256>>>();
    k_gcn_gemm<64><<<1250, 256>>>(gw1, gb1);

    // LSTM layer 0
    dim3 gx(1250, 4);
    k_xproj<<<gx, 256>>>(0, wih0, bih0, bhh0);
    k_lstm_layer<<<125, 256, LSTM_SMEM>>>(0, whh0);

    // LSTM layer 1
    k_xproj<<<gx, 256>>>(1, wih1, bih1, bhh1);
    k_lstm_layer<<<125, 256, LSTM_SMEM>>>(1, whh1);

    k_fc<<<(NN + 15) / 16, 256>>>(fcw, fcb, out);
}

// round 10
// speedup vs baseline: 1.4346x; 1.0714x over previous
#include <cuda_runtime.h>
#include <math.h>

#define NN  10000
#define NE  160000
#define TT  12
#define FIN 32
#define HH  64

typedef unsigned long long ull;

__device__ __forceinline__ ull ffma2(ull a, ull b, ull c){
    ull d; asm("fma.rn.f32x2 %0, %1, %2, %3;" : "=l"(d) : "l"(a), "l"(b), "l"(c)); return d;
}
__device__ __forceinline__ ull pack2(float lo, float hi){
    ull r; asm("mov.b64 %0, {%1, %2};" : "=l"(r) : "f"(lo), "f"(hi)); return r;
}
__device__ __forceinline__ void unpack2(ull v, float& lo, float& hi){
    asm("mov.b64 {%0, %1}, %2;" : "=f"(lo), "=f"(hi) : "l"(v));
}
__device__ __forceinline__ float tanha(float x){
    float y; asm("tanh.approx.f32 %0, %1;" : "=f"(y) : "f"(x)); return y;
}
__device__ __forceinline__ float fsig(float x){ return 0.5f * tanha(0.5f * x) + 0.5f; }

__device__ int   g_is64;
__device__ int   g_cnt[NN];
__device__ int   g_off[NN];
__device__ int   g_cur[NN];
__device__ int   g_src[NE];
__device__ int   g_bsum[80];
__device__ float g_dis[NN];
__device__ float g_aggx[NN * TT * FIN];
__device__ float g_h0  [NN * TT * HH];
__device__ float g_agg1[NN * TT * HH];
__device__ float g_hs0 [NN * TT * HH];
__device__ float g_pre [NN * TT * 256];     // float4 layout: [row][hcol]{i,f,g,o}
__device__ float g_hlast[NN * HH];

// ---------- CSR build ----------
__global__ void k_init(const int* __restrict__ w){
    int i = blockIdx.x * blockDim.x + threadIdx.x;
    if (i < NN) g_cnt[i] = 0;
    if (blockIdx.x == 0 && threadIdx.x == 0){
        int any = 0;
        #pragma unroll
        for (int j = 1; j < 129; j += 2) any |= w[j];
        g_is64 = (any == 0) ? 1 : 0;
    }
}

__global__ void k_count(const void* __restrict__ ei){
    int e = blockIdx.x * blockDim.x + threadIdx.x;
    if (e >= NE) return;
    int c = g_is64 ? (int)((const long long*)ei)[NE + e]
                   : ((const int*)ei)[NE + e];
    atomicAdd(&g_cnt[c], 1);
}

__global__ void k_scan1(){
    int b = blockIdx.x, t = threadIdx.x;
    int i = b * 128 + t;
    int v = (i < NN) ? g_cnt[i] : 0;
    int lane = t & 31, w = t >> 5;
    int s = v;
    #pragma unroll
    for (int d = 16; d > 0; d >>= 1) s += __shfl_down_sync(0xffffffffu, s, d);
    __shared__ int ws[4];
    if (lane == 0) ws[w] = s;
    __syncthreads();
    if (t == 0) g_bsum[b] = ws[0] + ws[1] + ws[2] + ws[3];
}

__global__ void k_scan3(){
    int b = blockIdx.x, t = threadIdx.x;
    __shared__ int sbase;
    __shared__ int ws[4];
    if (t < 32){
        int s = 0;
        for (int i = t; i < b; i += 32) s += g_bsum[i];
        #pragma unroll
        for (int d = 16; d > 0; d >>= 1) s += __shfl_down_sync(0xffffffffu, s, d);
        if (t == 0) sbase = s;
    }
    int i = b * 128 + t;
    int v = (i < NN) ? g_cnt[i] : 0;
    int lane = t & 31, w = t >> 5;
    int incl = v;
    #pragma unroll
    for (int d = 1; d < 32; d <<= 1){
        int o = __shfl_up_sync(0xffffffffu, incl, d);
        if (lane >= d) incl += o;
    }
    if (lane == 31) ws[w] = incl;
    __syncthreads();
    int base = sbase;
    for (int k = 0; k < w; ++k) base += ws[k];
    if (i < NN){
        g_off[i] = base + incl - v;
        g_cur[i] = 0;
        g_dis[i] = rsqrtf((float)(v + 1));
    }
}

__global__ void k_fill(const void* __restrict__ ei){
    int e = blockIdx.x * blockDim.x + threadIdx.x;
    if (e >= NE) return;
    int r, c;
    if (g_is64){
        r = (int)((const long long*)ei)[e];
        c = (int)((const long long*)ei)[NE + e];
    } else {
        r = ((const int*)ei)[e];
        c = ((const int*)ei)[NE + e];
    }
    int p = atomicAdd(&g_cur[c], 1);
    g_src[g_off[c] + p] = r;
}

// ---------- aggregations ----------
__global__ void k_agg_x(const float* __restrict__ x){
    int c   = blockIdx.x;
    int off = g_off[c], len = g_cnt[c];
    float dc = g_dis[c];
    int t = threadIdx.x;
    int p0 = t, p1 = t + 128, p2 = t + 256;
    int b0 = (p0 >> 5) * (NN * FIN) + (p0 & 31);
    int b1 = (p1 >> 5) * (NN * FIN) + (p1 & 31);
    int b2 = (p2 >> 5) * (NN * FIN) + (p2 & 31);
    int cb = c * FIN;
    float a0 = dc * x[b0 + cb];
    float a1 = dc * x[b1 + cb];
    float a2 = dc * x[b2 + cb];
    for (int e = 0; e < len; ++e){
        int r = g_src[off + e];
        float dr = g_dis[r];
        int rb = r * FIN;
        a0 += dr * x[b0 + rb];
        a1 += dr * x[b1 + rb];
        a2 += dr * x[b2 + rb];
    }
    g_aggx[c * 384 + p0] = dc * a0;
    g_aggx[c * 384 + p1] = dc * a1;
    g_aggx[c * 384 + p2] = dc * a2;
}

__global__ void k_agg_h(){
    int c   = blockIdx.x;
    int off = g_off[c], len = g_cnt[c];
    float dc = g_dis[c];
    int t = threadIdx.x;
    int cb = c * 768;
    float a0 = dc * g_h0[cb + t];
    float a1 = dc * g_h0[cb + t + 256];
    float a2 = dc * g_h0[cb + t + 512];
    for (int e = 0; e < len; ++e){
        int r = g_src[off + e];
        float dr = g_dis[r];
        int rb = r * 768;
        a0 += dr * g_h0[rb + t];
        a1 += dr * g_h0[rb + t + 256];
        a2 += dr * g_h0[rb + t + 512];
    }
    g_agg1[cb + t]       = dc * a0;
    g_agg1[cb + t + 256] = dc * a1;
    g_agg1[cb + t + 512] = dc * a2;
}

// ---------- GCN layer 0 GEMM: g_h0 = relu(g_aggx @ W + b) ----------
__global__ __launch_bounds__(256)
void k_gcn_gemm0(const float* __restrict__ W, const float* __restrict__ bvec){
    __shared__ __align__(16) float A_s[32 * 98];
    __shared__ float W_s[32 * 64];
    int t  = threadIdx.x;
    int nb = blockIdx.x * 96;

    for (int idx = t; idx < 32 * 64; idx += 256) W_s[idx] = W[idx];
    for (int idx = t; idx < 96 * 32; idx += 256){
        int n = idx >> 5, k = idx & 31;
        A_s[k * 98 + n] = g_aggx[(nb + n) * 32 + k];
    }
    __syncthreads();

    int jj = t & 31, pg = t >> 5;
    ull acc[6][2];
    #pragma unroll
    for (int p = 0; p < 6; ++p){ acc[p][0] = 0ull; acc[p][1] = 0ull; }

    #pragma unroll 8
    for (int k = 0; k < 32; ++k){
        float w0 = W_s[k * 64 + jj], w1 = W_s[k * 64 + jj + 32];
        ull W0 = pack2(w0, w0), W1 = pack2(w1, w1);
        const float* Ar = &A_s[k * 98 + pg * 12];
        #pragma unroll
        for (int p = 0; p < 6; ++p){
            ull a = *(const ull*)(Ar + 2 * p);
            acc[p][0] = ffma2(a, W0, acc[p][0]);
            acc[p][1] = ffma2(a, W1, acc[p][1]);
        }
    }
    float b0 = bvec[jj], b1 = bvec[jj + 32];
    #pragma unroll
    for (int p = 0; p < 6; ++p){
        float v0l, v0h, v1l, v1h;
        unpack2(acc[p][0], v0l, v0h);
        unpack2(acc[p][1], v1l, v1h);
        int row = nb + pg * 12 + 2 * p;
        g_h0[row * 64 + jj]            = fmaxf(v0l + b0, 0.f);
        g_h0[row * 64 + jj + 32]       = fmaxf(v1l + b1, 0.f);
        g_h0[(row + 1) * 64 + jj]      = fmaxf(v0h + b0, 0.f);
        g_h0[(row + 1) * 64 + jj + 32] = fmaxf(v1h + b1, 0.f);
    }
}

// ---------- fused GCN layer 1 + LSTM-0 input projection ----------
// h1 = relu(g_agg1 @ W1 + b1) kept in smem; g_pre = h1 @ Wih0^T + (bih0+bhh0)
#define GX_SMEM (25152 * 4)
__global__ __launch_bounds__(256)
void k_gcn1x(const float* __restrict__ W1, const float* __restrict__ b1,
             const float* __restrict__ wih, const float* __restrict__ bih,
             const float* __restrict__ bhh){
    extern __shared__ float sm[];
    float* A_s  = sm;             // 64 x 98  (agg1 tile, [k][n])
    float* W1_s = sm + 6272;      // 64 x 64
    float* b1_s = sm + 10368;     // 64
    float* A2_s = sm + 10432;     // 64 x 98  (h1 tile, [col][n])
    float* Wi_s = sm + 16704;     // 128 x 65
    float* bb_s = sm + 25024;     // 128
    int t  = threadIdx.x;
    int nb = blockIdx.x * 96;
    int jj = t & 31, pg = t >> 5;

    for (int idx = t; idx < 4096; idx += 256) W1_s[idx] = W1[idx];
    if (t < 64) b1_s[t] = b1[t];
    for (int idx = t; idx < 96 * 64; idx += 256){
        int n = idx >> 6, k = idx & 63;
        A_s[k * 98 + n] = g_agg1[(nb + n) * 64 + k];
    }
    __syncthreads();

    {   // GEMM1: 96 x 64
        ull acc[6][2];
        #pragma unroll
        for (int p = 0; p < 6; ++p){ acc[p][0] = 0ull; acc[p][1] = 0ull; }
        #pragma unroll 8
        for (int k = 0; k < 64; ++k){
            float w0 = W1_s[k * 64 + jj], w1 = W1_s[k * 64 + jj + 32];
            ull W0 = pack2(w0, w0), W1v = pack2(w1, w1);
            const float* Ar = &A_s[k * 98 + pg * 12];
            #pragma unroll
            for (int p = 0; p < 6; ++p){
                ull a = *(const ull*)(Ar + 2 * p);
                acc[p][0] = ffma2(a, W0, acc[p][0]);
                acc[p][1] = ffma2(a, W1v, acc[p][1]);
            }
        }
        float bb0 = b1_s[jj], bb1 = b1_s[jj + 32];
        #pragma unroll
        for (int p = 0; p < 6; ++p){
            float v0l, v0h, v1l, v1h;
            unpack2(acc[p][0], v0l, v0h);
            unpack2(acc[p][1], v1l, v1h);
            int n0 = pg * 12 + 2 * p;
            A2_s[jj * 98 + n0]            = fmaxf(v0l + bb0, 0.f);
            A2_s[jj * 98 + n0 + 1]        = fmaxf(v0h + bb0, 0.f);
            A2_s[(jj + 32) * 98 + n0]     = fmaxf(v1l + bb1, 0.f);
            A2_s[(jj + 32) * 98 + n0 + 1] = fmaxf(v1h + bb1, 0.f);
        }
    }
    __syncthreads();

    for (int half = 0; half < 2; ++half){
        for (int idx = t; idx < 128 * 64; idx += 256){
            int r = idx >> 6, k = idx & 63;
            int grow = (r >> 5) * 64 + half * 32 + (r & 31);
            Wi_s[r * 65 + k] = wih[grow * 64 + k];
        }
        if (t < 128){
            int grow = (t >> 5) * 64 + half * 32 + (t & 31);
            bb_s[t] = bih[grow] + bhh[grow];
        }
        __syncthreads();

        ull acc2[6][4];
        #pragma unroll
        for (int p = 0; p < 6; ++p)
            #pragma unroll
            for (int g = 0; g < 4; ++g) acc2[p][g] = 0ull;

        #pragma unroll 4
        for (int k = 0; k < 64; ++k){
            const float* Ar = &A2_s[k * 98 + pg * 12];
            ull a0 = *(const ull*)(Ar + 0);
            ull a1 = *(const ull*)(Ar + 2);
            ull a2 = *(const ull*)(Ar + 4);
            ull a3 = *(const ull*)(Ar + 6);
            ull a4 = *(const ull*)(Ar + 8);
            ull a5 = *(const ull*)(Ar + 10);
            #pragma unroll
            for (int g = 0; g < 4; ++g){
                float w = Wi_s[(g * 32 + jj) * 65 + k];
                ull W2 = pack2(w, w);
                acc2[0][g] = ffma2(a0, W2, acc2[0][g]);
                acc2[1][g] = ffma2(a1, W2, acc2[1][g]);
                acc2[2][g] = ffma2(a2, W2, acc2[2][g]);
                acc2[3][g] = ffma2(a3, W2, acc2[3][g]);
                acc2[4][g] = ffma2(a4, W2, acc2[4][g]);
                acc2[5][g] = ffma2(a5, W2, acc2[5][g]);
            }
        }
        float bi = bb_s[jj], bf = bb_s[32 + jj], bg = bb_s[64 + jj], bo = bb_s[96 + jj];
        int hcol = half * 32 + jj;
        #pragma unroll
        for (int p = 0; p < 6; ++p){
            float i0, i1, f0, f1, g0, g1, o0, o1;
            unpack2(acc2[p][0], i0, i1);
            unpack2(acc2[p][1], f0, f1);
            unpack2(acc2[p][2], g0, g1);
            unpack2(acc2[p][3], o0, o1);
            int row = nb + pg * 12 + 2 * p;
            float4 v0 = make_float4(i0 + bi, f0 + bf, g0 + bg, o0 + bo);
            float4 v1 = make_float4(i1 + bi, f1 + bf, g1 + bg, o1 + bo);
            ((float4*)g_pre)[row * 64 + hcol]       = v0;
            ((float4*)g_pre)[(row + 1) * 64 + hcol] = v1;
        }
        __syncthreads();
    }
}

// ---------- LSTM-1 input projection: g_pre = g_hs0 @ Wih1^T + bias ----------
#define XP_SMEM (14720 * 4)
__global__ __launch_bounds__(256)
void k_xproj2(const float* __restrict__ wih, const float* __restrict__ bih,
              const float* __restrict__ bhh){
    extern __shared__ float sm[];
    float* A_s  = sm;            // 64 x 98
    float* Wi_s = sm + 6272;     // 128 x 65
    float* bb_s = sm + 14592;    // 128
    int t  = threadIdx.x;
    int nb = blockIdx.x * 96;
    int cb = blockIdx.y * 32;
    int jj = t & 31, pg = t >> 5;

    for (int idx = t; idx < 128 * 64; idx += 256){
        int r = idx >> 6, k = idx & 63;
        int grow = (r >> 5) * 64 + cb + (r & 31);
        Wi_s[r * 65 + k] = wih[grow * 64 + k];
    }
    if (t < 128){
        int grow = (t >> 5) * 64 + cb + (t & 31);
        bb_s[t] = bih[grow] + bhh[grow];
    }
    for (int idx = t; idx < 96 * 64; idx += 256){
        int n = idx >> 6, k = idx & 63;
        A_s[k * 98 + n] = g_hs0[(nb + n) * 64 + k];
    }
    __syncthreads();

    ull acc2[6][4];
    #pragma unroll
    for (int p = 0; p < 6; ++p)
        #pragma unroll
        for (int g = 0; g < 4; ++g) acc2[p][g] = 0ull;

    #pragma unroll 4
    for (int k = 0; k < 64; ++k){
        const float* Ar = &A_s[k * 98 + pg * 12];
        ull a0 = *(const ull*)(Ar + 0);
        ull a1 = *(const ull*)(Ar + 2);
        ull a2 = *(const ull*)(Ar + 4);
        ull a3 = *(const ull*)(Ar + 6);
        ull a4 = *(const ull*)(Ar + 8);
        ull a5 = *(const ull*)(Ar + 10);
        #pragma unroll
        for (int g = 0; g < 4; ++g){
            float w = Wi_s[(g * 32 + jj) * 65 + k];
            ull W2 = pack2(w, w);
            acc2[0][g] = ffma2(a0, W2, acc2[0][g]);
            acc2[1][g] = ffma2(a1, W2, acc2[1][g]);
            acc2[2][g] = ffma2(a2, W2, acc2[2][g]);
            acc2[3][g] = ffma2(a3, W2, acc2[3][g]);
            acc2[4][g] = ffma2(a4, W2, acc2[4][g]);
            acc2[5][g] = ffma2(a5, W2, acc2[5][g]);
        }
    }
    float bi = bb_s[jj], bf = bb_s[32 + jj], bg = bb_s[64 + jj], bo = bb_s[96 + jj];
    int hcol = cb + jj;
    #pragma unroll
    for (int p = 0; p < 6; ++p){
        float i0, i1, f0, f1, g0, g1, o0, o1;
        unpack2(acc2[p][0], i0, i1);
        unpack2(acc2[p][1], f0, f1);
        unpack2(acc2[p][2], g0, g1);
        unpack2(acc2[p][3], o0, o1);
        int row = nb + pg * 12 + 2 * p;
        ((float4*)g_pre)[row * 64 + hcol]       = make_float4(i0 + bi, f0 + bf, g0 + bg, o0 + bo);
        ((float4*)g_pre)[(row + 1) * 64 + hcol] = make_float4(i1 + bi, f1 + bf, g1 + bg, o1 + bo);
    }
}

// ---------- persistent per-layer LSTM: 125 blocks x 80 nodes, 12 steps ----------
#define LSTM_SMEM ((256 * 65 + 64 * 82 + 64 * 82) * 4)

__global__ __launch_bounds__(256, 1)
void k_lstm_layer(int layer, const float* __restrict__ whh){
    extern __shared__ float smem[];
    float* W_s = smem;                 // [c 0..255][kk 0..63], pitch 65
    float* h_s = smem + 256 * 65;      // [k 0..63][n 0..79], pitch 82
    float* c_s = h_s + 64 * 82;

    int t  = threadIdx.x;
    int jj = t & 31, wg = t >> 5;
    int nb = blockIdx.x * 80;

    for (int idx = t; idx < 256 * 64; idx += 256){
        int k = idx & 63, c = idx >> 6;
        W_s[c * 65 + k] = whh[idx];
    }
    for (int idx = t; idx < 64 * 82; idx += 256){
        h_s[idx] = 0.f;
        c_s[idx] = 0.f;
    }
    __syncthreads();

    for (int st = 0; st < TT; ++st){
        ull acc[8][5];
        #pragma unroll
        for (int g = 0; g < 8; ++g)
            #pragma unroll
            for (int p = 0; p < 5; ++p) acc[g][p] = 0ull;

        #pragma unroll 4
        for (int kk = 0; kk < 64; ++kk){
            const float* Ar = h_s + kk * 82 + wg * 10;
            ull a0 = *(const ull*)(Ar + 0);
            ull a1 = *(const ull*)(Ar + 2);
            ull a2 = *(const ull*)(Ar + 4);
            ull a3 = *(const ull*)(Ar + 6);
            ull a4 = *(const ull*)(Ar + 8);
            #pragma unroll
            for (int g = 0; g < 8; ++g){
                float w = W_s[(jj + 32 * g) * 65 + kk];
                ull W2 = pack2(w, w);
                acc[g][0] = ffma2(a0, W2, acc[g][0]);
                acc[g][1] = ffma2(a1, W2, acc[g][1]);
                acc[g][2] = ffma2(a2, W2, acc[g][2]);
                acc[g][3] = ffma2(a3, W2, acc[g][3]);
                acc[g][4] = ffma2(a4, W2, acc[g][4]);
            }
        }
        __syncthreads();

        #pragma unroll
        for (int p = 0; p < 5; ++p){
            #pragma unroll
            for (int hs2 = 0; hs2 < 2; ++hs2){
                int hcol = jj + 32 * hs2;
                float i0, i1, f0, f1, g0, g1, o0, o1;
                unpack2(acc[0 + hs2][p], i0, i1);
                unpack2(acc[2 + hs2][p], f0, f1);
                unpack2(acc[4 + hs2][p], g0, g1);
                unpack2(acc[6 + hs2][p], o0, o1);
                #pragma unroll
                for (int half = 0; half < 2; ++half){
                    int nloc = wg * 10 + 2 * p + half;
                    int node = nb + nloc;
                    float4 pv = ((const float4*)g_pre)[(node * TT + st) * 64 + hcol];
                    float iv = (half ? i1 : i0) + pv.x;
                    float fv = (half ? f1 : f0) + pv.y;
                    float gv = (half ? g1 : g0) + pv.z;
                    float ov = (half ? o1 : o0) + pv.w;
                    float cold = c_s[hcol * 82 + nloc];
                    float cn = fsig(fv) * cold + fsig(iv) * tanha(gv);
                    float hn = fsig(ov) * tanha(cn);
                    c_s[hcol * 82 + nloc] = cn;
                    h_s[hcol * 82 + nloc] = hn;
                    if (layer == 0)
                        g_hs0[(node * TT + st) * 64 + hcol] = hn;
                    else if (st == TT - 1)
                        g_hlast[node * 64 + hcol] = hn;
                }
            }
        }
        __syncthreads();
    }
}

// ---------- final FC ----------
__global__ void k_fc(const float* __restrict__ fw, const float* __restrict__ fb,
                     float* __restrict__ out){
    __shared__ float wsh[16 * 64];
    int t = threadIdx.x;
    for (int idx = t; idx < 1024; idx += 256){
        int k = idx >> 4, o = idx & 15;
        wsh[idx] = fw[o * 64 + k];
    }
    __syncthreads();
    int n = blockIdx.x * 16 + (t >> 4);
    int o = t & 15;
    if (n >= NN) return;
    float acc = fb[o];
    #pragma unroll
    for (int k = 0; k < 64; ++k) acc += g_hlast[n * 64 + k] * wsh[k * 16 + o];
    out[n * 16 + o] = acc;
}

extern "C" void kernel_launch(void* const* d_in, const int* in_sizes, int n_in,
                              void* d_out, int out_size){
    const float* x    = (const float*)d_in[0];
    const void*  ei   =               d_in[1];
    const float* gw0  = (const float*)d_in[2];
    const float* gb0  = (const float*)d_in[3];
    const float* gw1  = (const float*)d_in[4];
    const float* gb1  = (const float*)d_in[5];
    const float* wih0 = (const float*)d_in[6];
    const float* whh0 = (const float*)d_in[7];
    const float* bih0 = (const float*)d_in[8];
    const float* bhh0 = (const float*)d_in[9];
    const float* wih1 = (const float*)d_in[10];
    const float* whh1 = (const float*)d_in[11];
    const float* bih1 = (const float*)d_in[12];
    const float* bhh1 = (const float*)d_in[13];
    const float* fcw  = (const float*)d_in[14];
    const float* fcb  = (const float*)d_in[15];
    float* out = (float*)d_out;

    cudaFuncSetAttribute(k_lstm_layer, cudaFuncAttributeMaxDynamicSharedMemorySize, LSTM_SMEM);
    cudaFuncSetAttribute(k_gcn1x,      cudaFuncAttributeMaxDynamicSharedMemorySize, GX_SMEM);
    cudaFuncSetAttribute(k_xproj2,     cudaFuncAttributeMaxDynamicSharedMemorySize, XP_SMEM);

    // CSR build
    k_init <<<40, 256>>>((const int*)ei);
    k_count<<<(NE + 255) / 256, 256>>>(ei);
    k_scan1<<<79, 128>>>();
    k_scan3<<<79, 128>>>();
    k_fill <<<(NE + 255) / 256, 256>>>(ei);

    // GCN layer 0
    k_agg_x<<<NN, 128>>>(x);
    k_gcn_gemm0<<<1250, 256>>>(gw0, gb0);
    // GCN layer 1 fused with LSTM-0 input projection
    k_agg_h<<<NN, 256>>>();
    k_gcn1x<<<1250, 256, GX_SMEM>>>(gw1, gb1, wih0, bih0, bhh0);

    // LSTM layer 0
    k_lstm_layer<<<125, 256, LSTM_SMEM>>>(0, whh0);

    // LSTM layer 1
    {
        dim3 gx(1250, 2);
        k_xproj2<<<gx, 256, XP_SMEM>>>(wih1, bih1, bhh1);
    }
    k_lstm_layer<<<125, 256, LSTM_SMEM>>>(1, whh1);

    k_fc<<<(NN + 15) / 16, 256>>>(fcw, fcb, out);
}